// round 5
// baseline (speedup 1.0000x reference)
#include <cuda_runtime.h>
#include <cuda_bf16.h>
#include <cstdint>

// CRF NLL: B=1024, T=512, C=64. START=62, STOP=63, NEG_INF=-10000.
// Forward algorithm as per-step matvec against expT = exp(transitions) kept in
// registers (f32x2-packed columns). One warp per batch row, 2 tags per lane.
//
// Input binding: emissions = largest input, transitions = 4096 elements.
// tags vs mask (equal element counts) resolved on device: the buffer whose
// leading 16 words are all in {0,1} is the mask. Tags are loaded as int32
// (harness narrows int64); an int64 tag layout (odd words zero) is also
// detected and handled, and never reads beyond the int32 extent.

#define C_TAGS 64
#define T_LEN  512
#define START_TAG 62
#define STOP_TAG  63
#define NEG_INF_F (-10000.0f)
#define LOG2E 1.4426950408889634f
#define LN2   0.6931471805599453f
#define WARPS_PER_BLK 4

__device__ float g_res[4096];  // per-batch (logZ - gold)

// ---- packed f32x2 helpers (sm_100+) ----
__device__ __forceinline__ unsigned long long pack2(float x, float y) {
    unsigned long long r;
    asm("mov.b64 %0, {%1, %2};" : "=l"(r) : "f"(x), "f"(y));
    return r;
}
__device__ __forceinline__ void unpack2(unsigned long long v, float& x, float& y) {
    asm("mov.b64 {%0, %1}, %2;" : "=f"(x), "=f"(y) : "l"(v));
}
__device__ __forceinline__ unsigned long long ffma2(unsigned long long a,
                                                    unsigned long long b,
                                                    unsigned long long c) {
    unsigned long long d;
    asm("fma.rn.f32x2 %0, %1, %2, %3;" : "=l"(d) : "l"(a), "l"(b), "l"(c));
    return d;
}
__device__ __forceinline__ unsigned long long fadd2(unsigned long long a,
                                                    unsigned long long b) {
    unsigned long long d;
    asm("add.rn.f32x2 %0, %1, %2;" : "=l"(d) : "l"(a), "l"(b));
    return d;
}
__device__ __forceinline__ float ex2f(float x) {
    float y; asm("ex2.approx.f32 %0, %1;" : "=f"(y) : "f"(x)); return y;
}
__device__ __forceinline__ float lg2f(float x) {
    float y; asm("lg2.approx.f32 %0, %1;" : "=f"(y) : "f"(x)); return y;
}

// First 16 words all in {0,1}  =>  mask buffer.
__device__ __forceinline__ bool looks_like_mask(const unsigned int* p) {
    bool ok = true;
#pragma unroll
    for (int i = 0; i < 16; i++) ok &= (p[i] <= 1u);
    return ok;
}
// Odd words of first 16 all zero, even words <= 63  =>  int64 tag layout.
__device__ __forceinline__ bool looks_like_i64_tags(const unsigned int* p) {
    bool ok = true;
#pragma unroll
    for (int i = 0; i < 8; i++) ok &= (p[2 * i + 1] == 0u) && (p[2 * i] <= 63u);
    return ok;
}

__global__ void __launch_bounds__(WARPS_PER_BLK * 32)
crf_forward_kernel(const float* __restrict__ emissions,
                   const float* __restrict__ trans,
                   const void* __restrict__ candA,   // tags or mask
                   const void* __restrict__ candB,   // the other one
                   int B) {
    const int w = threadIdx.x >> 5;
    const int l = threadIdx.x & 31;
    const int b = blockIdx.x * WARPS_PER_BLK + w;
    if (b >= B) return;

    const unsigned int* pa = (const unsigned int*)candA;
    const unsigned int* pb = (const unsigned int*)candB;
    const bool a_is_mask = looks_like_mask(pa) && !looks_like_mask(pb);
    const unsigned int* tagw = a_is_mask ? pb : pa;
    const int* mask = (const int*)(a_is_mask ? candA : candB);
    // Tag element stride in 32-bit words (2 if the harness kept int64).
    const int tstride = looks_like_i64_tags(tagw) ? 2 : 1;

    const int j0 = 2 * l;
    const int j1 = 2 * l + 1;

    // Loop-invariant transition columns j0,j1, exponentiated, in registers.
    // col[i] = ( exp(trans[i][j0]), exp(trans[i][j1]) ).
    // exp(-10000) -> 0 exactly encodes forbidden transitions.
    unsigned long long col[C_TAGS];
#pragma unroll
    for (int i = 0; i < C_TAGS; i++) {
        float2 t2 = *reinterpret_cast<const float2*>(trans + i * C_TAGS + j0);
        col[i] = pack2(ex2f(t2.x * LOG2E), ex2f(t2.y * LOG2E));
    }
    const float ts0 = trans[j0 * C_TAGS + STOP_TAG];
    const float ts1 = trans[j1 * C_TAGS + STOP_TAG];

    // Per-warp shared buffer of duplicated probabilities p[i] = (p_i, p_i)
    __shared__ __align__(16) unsigned long long ps[WARPS_PER_BLK][C_TAGS];

    float a0 = (j0 == START_TAG) ? 0.0f : NEG_INF_F;
    float a1 = (j1 == START_TAG) ? 0.0f : NEG_INF_F;

    const float* emb = emissions + (size_t)b * T_LEN * C_TAGS;
    const int* mb = mask + (size_t)b * T_LEN;

    // Warp-uniform renormalization reference (math exact for any m):
    // t=0 exact (0 at START). Thereafter fmax(alpha[0], alpha[62]): while the
    // prefix is masked out, alpha[62]=0 dominates; after the first real step
    // alpha[62] is -1e4-ish (transitions into START forbidden) and alpha[0]
    // is within the small cross-tag spread of the true max.
    float m_ref = 0.0f;

    float2 e2 = *reinterpret_cast<const float2*>(emb + j0);
    int mk = mb[0];

#pragma unroll 1
    for (int t = 0; t < T_LEN; t++) {
        // Prefetch next step's emission + mask (off the dependent chain).
        float2 e2n = make_float2(0.0f, 0.0f);
        int mkn = 0;
        if (t + 1 < T_LEN) {
            e2n = *reinterpret_cast<const float2*>(emb + (t + 1) * C_TAGS + j0);
            mkn = mb[t + 1];
        }

        const float m = m_ref;
        float p0 = ex2f((a0 - m) * LOG2E);
        float p1 = ex2f((a1 - m) * LOG2E);
        ps[w][j0] = pack2(p0, p0);
        ps[w][j1] = pack2(p1, p1);
        __syncwarp();

        // s(j0,j1) = sum_i p_i * expT[i][{j0,j1}] -- 64 packed FMAs, 4 chains
        const ulonglong2* pv = reinterpret_cast<const ulonglong2*>(ps[w]);
        unsigned long long s0 = 0ull, s1 = 0ull, s2 = 0ull, s3 = 0ull;
#pragma unroll
        for (int k = 0; k < 16; k++) {
            ulonglong2 qa = pv[2 * k];
            ulonglong2 qb = pv[2 * k + 1];
            s0 = ffma2(qa.x, col[4 * k + 0], s0);
            s1 = ffma2(qa.y, col[4 * k + 1], s1);
            s2 = ffma2(qb.x, col[4 * k + 2], s2);
            s3 = ffma2(qb.y, col[4 * k + 3], s3);
        }
        unsigned long long ss = fadd2(fadd2(s0, s1), fadd2(s2, s3));
        float sx, sy;
        unpack2(ss, sx, sy);

        float na0 = m + lg2f(sx) * LN2 + e2.x;
        float na1 = m + lg2f(sy) * LN2 + e2.y;
        if (mk) { a0 = na0; a1 = na1; }

        // New warp-uniform reference for the next step (2 parallel shfls).
        float r0 = __shfl_sync(0xFFFFFFFFu, a0, 0);    // alpha[0]
        float r62 = __shfl_sync(0xFFFFFFFFu, a0, 31);  // alpha[62] (START col)
        m_ref = fmaxf(r0, r62);

        e2 = e2n;
        mk = mkn;
        __syncwarp();
    }

    // log-partition: logsumexp(alpha + trans[:, STOP])  (exact max, once)
    a0 += ts0;
    a1 += ts1;
    float m = fmaxf(a0, a1);
#pragma unroll
    for (int o = 16; o > 0; o >>= 1)
        m = fmaxf(m, __shfl_xor_sync(0xFFFFFFFFu, m, o));
    float s = ex2f((a0 - m) * LOG2E) + ex2f((a1 - m) * LOG2E);
#pragma unroll
    for (int o = 16; o > 0; o >>= 1)
        s += __shfl_xor_sync(0xFFFFFFFFu, s, o);
    float logZ = m + lg2f(s) * LN2;

    // Gold score (lane-parallel over t; contiguous-prefix mask assumption,
    // exact for the all-ones masks this problem generates).
    const unsigned int* tgb = tagw + (size_t)b * T_LEN * tstride;
    float g = 0.0f;
    int cnt = 0;
#pragma unroll 1
    for (int t = l; t < T_LEN; t += 32) {
        int mkt = mb[t];
        if (mkt) {
            int tg = (int)tgb[(size_t)t * tstride];
            int pvt = (t == 0) ? START_TAG : (int)tgb[(size_t)(t - 1) * tstride];
            g += emb[t * C_TAGS + tg] + trans[pvt * C_TAGS + tg];
        }
        cnt += mkt;
    }
#pragma unroll
    for (int o = 16; o > 0; o >>= 1) {
        g += __shfl_xor_sync(0xFFFFFFFFu, g, o);
        cnt += __shfl_xor_sync(0xFFFFFFFFu, cnt, o);
    }
    if (l == 0) {
        int last = (cnt > 0) ? (int)tgb[(size_t)(cnt - 1) * tstride] : START_TAG;
        float gold = g + trans[last * C_TAGS + STOP_TAG];
        g_res[b] = logZ - gold;
    }
}

__global__ void crf_reduce_kernel(float* __restrict__ out, int B) {
    __shared__ float sh[256];
    int t = threadIdx.x;
    float v = 0.0f;
    for (int i = t; i < B; i += 256) v += g_res[i];
    sh[t] = v;
    __syncthreads();
#pragma unroll
    for (int o = 128; o > 0; o >>= 1) {
        if (t < o) sh[t] += sh[t + o];
        __syncthreads();
    }
    if (t == 0) out[0] = sh[0] / (float)B;
}

extern "C" void kernel_launch(void* const* d_in, const int* in_sizes, int n_in,
                              void* d_out, int out_size) {
    // Resolve inputs by size, independent of metadata ordering:
    //   emissions   = largest input (B*T*C)
    //   transitions = C*C = 4096 elements
    //   tags/mask   = the remaining two -> resolved on device by value.
    int em_i = 0;
    for (int i = 1; i < n_in; i++)
        if (in_sizes[i] > in_sizes[em_i]) em_i = i;
    int tr_i = -1;
    for (int i = 0; i < n_in; i++)
        if (i != em_i && in_sizes[i] == C_TAGS * C_TAGS) { tr_i = i; break; }
    int rem[2], r = 0;
    for (int i = 0; i < n_in && r < 2; i++)
        if (i != em_i && i != tr_i) rem[r++] = i;

    const float* emissions = (const float*)d_in[em_i];
    const float* trans     = (const float*)d_in[tr_i];
    const void*  candA     = d_in[rem[0]];
    const void*  candB     = d_in[rem[1]];

    // B from emissions (dtype-independent): elements / (T*C)
    int B = in_sizes[em_i] / (T_LEN * C_TAGS);

    int blocks = (B + WARPS_PER_BLK - 1) / WARPS_PER_BLK;
    crf_forward_kernel<<<blocks, WARPS_PER_BLK * 32>>>(emissions, trans,
                                                       candA, candB, B);
    crf_reduce_kernel<<<1, 256>>>((float*)d_out, B);
}

// round 7
// speedup vs baseline: 1.9320x; 1.9320x over previous
#include <cuda_runtime.h>
#include <cuda_bf16.h>
#include <cstdint>

// CRF NLL: B=1024, T=512, C=64. START=62, STOP=63, NEG_INF=-10000.
// Forward algorithm as per-step matvec against expT = exp(transitions), kept in
// registers packed over the reduction index i: colA[k]=(expT[2k][j0],expT[2k+1][j0]).
// One warp per batch row, 2 tags per lane. Depth-4 emission prefetch pipeline,
// double-buffered p staging (1 syncwarp/step), 1-step-stale renorm reference.
// Final mean fused via arrival ticket (single kernel launch).

#define C_TAGS 64
#define T_LEN  512
#define START_TAG 62
#define STOP_TAG  63
#define NEG_INF_F (-10000.0f)
#define LOG2E 1.4426950408889634f
#define LN2   0.6931471805599453f
#define WARPS_PER_BLK 4
#define PF 4

__device__ float g_res[4096];   // per-batch (logZ - gold)
__device__ int   g_count = 0;   // arrival ticket (reset by last block each run)

// ---- packed f32x2 helpers (sm_100+) ----
__device__ __forceinline__ unsigned long long pack2(float x, float y) {
    unsigned long long r;
    asm("mov.b64 %0, {%1, %2};" : "=l"(r) : "f"(x), "f"(y));
    return r;
}
__device__ __forceinline__ void unpack2(unsigned long long v, float& x, float& y) {
    asm("mov.b64 {%0, %1}, %2;" : "=f"(x), "=f"(y) : "l"(v));
}
__device__ __forceinline__ unsigned long long ffma2(unsigned long long a,
                                                    unsigned long long b,
                                                    unsigned long long c) {
    unsigned long long d;
    asm("fma.rn.f32x2 %0, %1, %2, %3;" : "=l"(d) : "l"(a), "l"(b), "l"(c));
    return d;
}
__device__ __forceinline__ unsigned long long fadd2(unsigned long long a,
                                                    unsigned long long b) {
    unsigned long long d;
    asm("add.rn.f32x2 %0, %1, %2;" : "=l"(d) : "l"(a), "l"(b));
    return d;
}
__device__ __forceinline__ float ex2f(float x) {
    float y; asm("ex2.approx.f32 %0, %1;" : "=f"(y) : "f"(x)); return y;
}
__device__ __forceinline__ float lg2f(float x) {
    float y; asm("lg2.approx.f32 %0, %1;" : "=f"(y) : "f"(x)); return y;
}

// First 16 words all in {0,1}  =>  mask buffer.
__device__ __forceinline__ bool looks_like_mask(const unsigned int* p) {
    bool ok = true;
#pragma unroll
    for (int i = 0; i < 16; i++) ok &= (p[i] <= 1u);
    return ok;
}
// Odd words of first 16 all zero, even words <= 63  =>  int64 tag layout.
__device__ __forceinline__ bool looks_like_i64_tags(const unsigned int* p) {
    bool ok = true;
#pragma unroll
    for (int i = 0; i < 8; i++) ok &= (p[2 * i + 1] == 0u) && (p[2 * i] <= 63u);
    return ok;
}

__global__ void __launch_bounds__(WARPS_PER_BLK * 32)
crf_fused_kernel(const float* __restrict__ emissions,
                 const float* __restrict__ trans,
                 const void* __restrict__ candA,   // tags or mask
                 const void* __restrict__ candB,   // the other one
                 float* __restrict__ out, int B) {
    const int tid = threadIdx.x;
    const int w = tid >> 5;
    const int l = tid & 31;
    const int b = blockIdx.x * WARPS_PER_BLK + w;
    const bool active = (b < B);

    // p staging: double-buffered, packed pairs (p_{2l}, p_{2l+1}) per lane.
    __shared__ __align__(16) unsigned long long ps[WARPS_PER_BLK][2][32];
    __shared__ float red[WARPS_PER_BLK * 32];
    __shared__ int s_ticket;

    if (active) {
        const unsigned int* pa = (const unsigned int*)candA;
        const unsigned int* pb = (const unsigned int*)candB;
        const bool a_is_mask = looks_like_mask(pa) && !looks_like_mask(pb);
        const unsigned int* tagw = a_is_mask ? pb : pa;
        const int* mask = (const int*)(a_is_mask ? candA : candB);
        const int tstride = looks_like_i64_tags(tagw) ? 2 : 1;

        const int j0 = 2 * l;
        const int j1 = 2 * l + 1;

        // colA[k] = (expT[2k][j0], expT[2k+1][j0]); colB likewise for j1.
        unsigned long long colA[32], colB[32];
#pragma unroll
        for (int k = 0; k < 32; k++) {
            float2 ta = *reinterpret_cast<const float2*>(trans + (2 * k) * C_TAGS + j0);
            float2 tb = *reinterpret_cast<const float2*>(trans + (2 * k + 1) * C_TAGS + j0);
            colA[k] = pack2(ex2f(ta.x * LOG2E), ex2f(tb.x * LOG2E));
            colB[k] = pack2(ex2f(ta.y * LOG2E), ex2f(tb.y * LOG2E));
        }
        const float ts0 = trans[j0 * C_TAGS + STOP_TAG];
        const float ts1 = trans[j1 * C_TAGS + STOP_TAG];

        float a0 = (j0 == START_TAG) ? 0.0f : NEG_INF_F;
        float a1 = NEG_INF_F;  // odd tags: 63=STOP and others never START

        const float* emb = emissions + (size_t)b * T_LEN * C_TAGS;
        const int* mb = mask + (size_t)b * T_LEN;

        // 1-step-stale warp-uniform renorm reference (math exact for any m).
        float m_stale = 0.0f;

        // Depth-PF emission prefetch pipeline + int4 mask prefetch.
        float2 ebuf[PF];
#pragma unroll
        for (int u = 0; u < PF; u++)
            ebuf[u] = *reinterpret_cast<const float2*>(emb + u * C_TAGS + j0);
        int4 mk4 = *reinterpret_cast<const int4*>(mb);

#pragma unroll 1
        for (int tb4 = 0; tb4 < T_LEN; tb4 += PF) {
            int mnext = (tb4 + PF <= T_LEN - PF) ? (tb4 + PF) : (T_LEN - PF);
            int4 mk4n = *reinterpret_cast<const int4*>(mb + mnext);
            int mks[PF] = {mk4.x, mk4.y, mk4.z, mk4.w};
#pragma unroll
            for (int u = 0; u < PF; u++) {
                const int t = tb4 + u;
                const float2 e2 = ebuf[u];
                const int mk = mks[u];
                // Prefetch emission for t+PF (clamped, branch-free).
                int tp = (t + PF < T_LEN) ? (t + PF) : (T_LEN - 1);
                ebuf[u] = *reinterpret_cast<const float2*>(emb + tp * C_TAGS + j0);

                const float m = m_stale;
                // Shfl the pre-update alpha now; consumed next step.
                float r0 = __shfl_sync(0xFFFFFFFFu, a0, 0);
                float r62 = __shfl_sync(0xFFFFFFFFu, a0, 31);

                float p0 = ex2f((a0 - m) * LOG2E);
                float p1 = ex2f((a1 - m) * LOG2E);
                ps[w][u & 1][l] = pack2(p0, p1);
                __syncwarp();

                const ulonglong2* pv =
                    reinterpret_cast<const ulonglong2*>(ps[w][u & 1]);
                unsigned long long A0 = 0, A1 = 0, A2 = 0, A3 = 0;
                unsigned long long B0 = 0, B1 = 0, B2 = 0, B3 = 0;
#pragma unroll
                for (int k = 0; k < 8; k++) {
                    ulonglong2 qa = pv[2 * k];
                    ulonglong2 qb = pv[2 * k + 1];
                    A0 = ffma2(qa.x, colA[4 * k + 0], A0);
                    A1 = ffma2(qa.y, colA[4 * k + 1], A1);
                    A2 = ffma2(qb.x, colA[4 * k + 2], A2);
                    A3 = ffma2(qb.y, colA[4 * k + 3], A3);
                    B0 = ffma2(qa.x, colB[4 * k + 0], B0);
                    B1 = ffma2(qa.y, colB[4 * k + 1], B1);
                    B2 = ffma2(qb.x, colB[4 * k + 2], B2);
                    B3 = ffma2(qb.y, colB[4 * k + 3], B3);
                }
                unsigned long long SA = fadd2(fadd2(A0, A1), fadd2(A2, A3));
                unsigned long long SB = fadd2(fadd2(B0, B1), fadd2(B2, B3));
                float ax, ay, bx, by;
                unpack2(SA, ax, ay);
                unpack2(SB, bx, by);
                float na0 = m + lg2f(ax + ay) * LN2 + e2.x;
                float na1 = m + lg2f(bx + by) * LN2 + e2.y;
                if (mk) { a0 = na0; a1 = na1; }
                m_stale = fmaxf(r0, r62);
            }
            mk4 = mk4n;
        }

        // log-partition: logsumexp(alpha + trans[:, STOP])  (exact max, once)
        a0 += ts0;
        a1 += ts1;
        float m = fmaxf(a0, a1);
#pragma unroll
        for (int o = 16; o > 0; o >>= 1)
            m = fmaxf(m, __shfl_xor_sync(0xFFFFFFFFu, m, o));
        float s = ex2f((a0 - m) * LOG2E) + ex2f((a1 - m) * LOG2E);
#pragma unroll
        for (int o = 16; o > 0; o >>= 1)
            s += __shfl_xor_sync(0xFFFFFFFFu, s, o);
        float logZ = m + lg2f(s) * LN2;

        // Gold score (lane-parallel over t; contiguous-prefix mask assumption,
        // exact for the all-ones masks this problem generates).
        const unsigned int* tgb = tagw + (size_t)b * T_LEN * tstride;
        float g = 0.0f;
        int cnt = 0;
#pragma unroll 1
        for (int t = l; t < T_LEN; t += 32) {
            int mkt = mb[t];
            if (mkt) {
                int tg = (int)tgb[(size_t)t * tstride];
                int pvt = (t == 0) ? START_TAG
                                   : (int)tgb[(size_t)(t - 1) * tstride];
                g += emb[t * C_TAGS + tg] + trans[pvt * C_TAGS + tg];
            }
            cnt += mkt;
        }
#pragma unroll
        for (int o = 16; o > 0; o >>= 1) {
            g += __shfl_xor_sync(0xFFFFFFFFu, g, o);
            cnt += __shfl_xor_sync(0xFFFFFFFFu, cnt, o);
        }
        if (l == 0) {
            int last = (cnt > 0) ? (int)tgb[(size_t)(cnt - 1) * tstride]
                                 : START_TAG;
            float gold = g + trans[last * C_TAGS + STOP_TAG];
            g_res[b] = logZ - gold;
            __threadfence();  // publish before ticket
        }
    }

    // ---- fused mean: last block to arrive reduces all of g_res ----
    __syncthreads();
    if (tid == 0) s_ticket = atomicAdd(&g_count, 1);
    __syncthreads();
    if (s_ticket == (int)gridDim.x - 1) {
        __threadfence();  // acquire
        float v = 0.0f;
        for (int i = tid; i < B; i += WARPS_PER_BLK * 32) v += g_res[i];
        red[tid] = v;
        __syncthreads();
#pragma unroll
        for (int o = WARPS_PER_BLK * 16; o > 0; o >>= 1) {
            if (tid < o) red[tid] += red[tid + o];
            __syncthreads();
        }
        if (tid == 0) {
            out[0] = red[0] / (float)B;
            g_count = 0;  // reset for next graph replay
        }
    }
}

extern "C" void kernel_launch(void* const* d_in, const int* in_sizes, int n_in,
                              void* d_out, int out_size) {
    // Resolve inputs by size, independent of metadata ordering:
    //   emissions   = largest input (B*T*C)
    //   transitions = C*C = 4096 elements
    //   tags/mask   = the remaining two -> resolved on device by value.
    int em_i = 0;
    for (int i = 1; i < n_in; i++)
        if (in_sizes[i] > in_sizes[em_i]) em_i = i;
    int tr_i = -1;
    for (int i = 0; i < n_in; i++)
        if (i != em_i && in_sizes[i] == C_TAGS * C_TAGS) { tr_i = i; break; }
    int rem[2], r = 0;
    for (int i = 0; i < n_in && r < 2; i++)
        if (i != em_i && i != tr_i) rem[r++] = i;

    const float* emissions = (const float*)d_in[em_i];
    const float* trans     = (const float*)d_in[tr_i];
    const void*  candA     = d_in[rem[0]];
    const void*  candB     = d_in[rem[1]];

    int B = in_sizes[em_i] / (T_LEN * C_TAGS);
    int blocks = (B + WARPS_PER_BLK - 1) / WARPS_PER_BLK;
    crf_fused_kernel<<<blocks, WARPS_PER_BLK * 32>>>(emissions, trans,
                                                     candA, candB,
                                                     (float*)d_out, B);
}